// round 1
// baseline (speedup 1.0000x reference)
#include <cuda_runtime.h>
#include <cuda_fp16.h>

#define HID   1024
#define HEADS 16
#define DK    64
#define BATCH 2
#define SEQ   2048
#define TOK   (BATCH * SEQ)   // 4096
#define QK_SCALE 0.125f       // 64^-0.5

// ---------------- scratch (static device globals; no allocs allowed) ----------
__device__ __half g_W16[4][HID * HID];                  // Wq,Wk,Wv,Wo in fp16
__device__ __half g_Qh[BATCH * HEADS * SEQ * DK];       // [b,h,s,d], pre-scaled
__device__ __half g_Kh[BATCH * HEADS * SEQ * DK];       // [b,h,s,d]
__device__ __half g_Vt[BATCH * HEADS * DK * SEQ];       // [b,h,d,s]  (transposed!)
__device__ __half g_attn[TOK * HID];                    // [token, h*64+d]

// ---------------- helpers ----------------------------------------------------
__device__ __forceinline__ void mma16816(float* c, const unsigned* a,
                                         unsigned b0, unsigned b1) {
    asm volatile(
        "mma.sync.aligned.m16n8k16.row.col.f32.f16.f16.f32 "
        "{%0,%1,%2,%3}, {%4,%5,%6,%7}, {%8,%9}, {%0,%1,%2,%3};\n"
        : "+f"(c[0]), "+f"(c[1]), "+f"(c[2]), "+f"(c[3])
        : "r"(a[0]), "r"(a[1]), "r"(a[2]), "r"(a[3]), "r"(b0), "r"(b1));
}

__device__ __forceinline__ unsigned packh2(float x, float y) {
    __half2 h = __floats2half2_rn(x, y);
    return reinterpret_cast<unsigned&>(h);
}

// ---------------- weight conversion ------------------------------------------
__global__ void cvt_weights(const float* __restrict__ wq, const float* __restrict__ wk,
                            const float* __restrict__ wv, const float* __restrict__ wo) {
    int i = blockIdx.x * blockDim.x + threadIdx.x;   // over HID*HID/4 float4s
    const float4* srcs[4] = {(const float4*)wq, (const float4*)wk,
                             (const float4*)wv, (const float4*)wo};
#pragma unroll
    for (int w = 0; w < 4; w++) {
        float4 v = srcs[w][i];
        __half2* d = (__half2*)&g_W16[w][i * 4];
        d[0] = __floats2half2_rn(v.x, v.y);
        d[1] = __floats2half2_rn(v.z, v.w);
    }
}

// ---------------- projection GEMM: Y = A(fp32) @ W^T, head-layout epilogue ----
// Block tile 128x64, K-step 32. 8 warps: 4 (m) x 2 (n), each 32x32.
__global__ __launch_bounds__(256) void gemm_head(const float* __restrict__ A, int mode) {
    __shared__ __half Asm[128][40];
    __shared__ __half Bsm[64][40];

    const __half* W = g_W16[mode];
    int tid = threadIdx.x, lane = tid & 31, wid = tid >> 5;
    int g = lane >> 2, tg = lane & 3;
    int wm = wid & 3, wn = wid >> 2;
    int rowB = blockIdx.y * 128, colB = blockIdx.x * 64;

    float acc[2][4][4] = {};

    for (int kb = 0; kb < HID; kb += 32) {
        __syncthreads();
        // A tile 128x32: fp32 gmem -> fp16 smem
#pragma unroll
        for (int i = 0; i < 4; i++) {
            int f = tid + i * 256;                 // 1024 float4 slots
            int r = f >> 3, c4 = (f & 7) * 4;
            float4 v = *(const float4*)(A + (size_t)(rowB + r) * HID + kb + c4);
            *(__half2*)&Asm[r][c4]     = __floats2half2_rn(v.x, v.y);
            *(__half2*)&Asm[r][c4 + 2] = __floats2half2_rn(v.z, v.w);
        }
        // B tile 64x32 (W rows = output cols)
        {
            int r = tid >> 2, c8 = (tid & 3) * 8;
            *(uint4*)&Bsm[r][c8] =
                *(const uint4*)(W + (size_t)(colB + r) * HID + kb + c8);
        }
        __syncthreads();

#pragma unroll
        for (int kk = 0; kk < 32; kk += 16) {
            unsigned a[2][4];
#pragma unroll
            for (int mi = 0; mi < 2; mi++) {
                int r = wm * 32 + mi * 16 + g;
                a[mi][0] = *(unsigned*)&Asm[r][kk + tg * 2];
                a[mi][1] = *(unsigned*)&Asm[r + 8][kk + tg * 2];
                a[mi][2] = *(unsigned*)&Asm[r][kk + 8 + tg * 2];
                a[mi][3] = *(unsigned*)&Asm[r + 8][kk + 8 + tg * 2];
            }
#pragma unroll
            for (int nj = 0; nj < 4; nj++) {
                int c = wn * 32 + nj * 8 + g;
                unsigned b0 = *(unsigned*)&Bsm[c][kk + tg * 2];
                unsigned b1 = *(unsigned*)&Bsm[c][kk + 8 + tg * 2];
                mma16816(acc[0][nj], a[0], b0, b1);
                mma16816(acc[1][nj], a[1], b0, b1);
            }
        }
    }

    // epilogue
    float scale = (mode == 0) ? QK_SCALE : 1.0f;
    __half* dst = (mode == 0) ? g_Qh : (mode == 1) ? g_Kh : g_Vt;
#pragma unroll
    for (int mi = 0; mi < 2; mi++) {
#pragma unroll
        for (int nj = 0; nj < 4; nj++) {
            int r0 = rowB + wm * 32 + mi * 16 + g;
            int c0 = colB + wn * 32 + nj * 8 + tg * 2;
            int b = r0 >> 11, s = r0 & (SEQ - 1);
            int h = c0 >> 6, d = c0 & 63;
            int bh = b * HEADS + h;
            if (mode == 2) {
                // transposed layout [bh][d][s]
                size_t base = ((size_t)bh * DK + d) * SEQ + s;
                dst[base]            = __float2half_rn(acc[mi][nj][0]);
                dst[base + SEQ]      = __float2half_rn(acc[mi][nj][1]);
                dst[base + 8]        = __float2half_rn(acc[mi][nj][2]);
                dst[base + SEQ + 8]  = __float2half_rn(acc[mi][nj][3]);
            } else {
                size_t base = ((size_t)bh * SEQ + s) * DK + d;
                *(__half2*)(dst + base) =
                    __floats2half2_rn(acc[mi][nj][0] * scale, acc[mi][nj][1] * scale);
                *(__half2*)(dst + base + 8 * DK) =
                    __floats2half2_rn(acc[mi][nj][2] * scale, acc[mi][nj][3] * scale);
            }
        }
    }
}

// ---------------- flash attention --------------------------------------------
// grid: (SEQ/64, BATCH*HEADS), 128 threads (4 warps), each warp = 16 query rows.
__global__ __launch_bounds__(128) void flash(const unsigned char* __restrict__ mask) {
    __shared__ __half Qsm[64][72];
    __shared__ __half Ksm[64][72];
    __shared__ __half Vtsm[64][72];   // [d][key]
    __shared__ unsigned char Msm[64][64];
    __shared__ int maskAny[2];

    int tid = threadIdx.x, lane = tid & 31, wid = tid >> 5;
    int g = lane >> 2, tg = lane & 3;
    int bh = blockIdx.y, b = bh >> 4, h = bh & 15;
    int qt = blockIdx.x;

    const __half* Qp = g_Qh + (size_t)bh * SEQ * DK + (size_t)qt * 64 * DK;
    const __half* Kp = g_Kh + (size_t)bh * SEQ * DK;
    const __half* Vp = g_Vt + (size_t)bh * DK * SEQ;
    const unsigned char* Mp = mask + (size_t)b * SEQ * SEQ + (size_t)(qt * 64) * SEQ;

    if (tid < 2) maskAny[tid] = 0;
    // Q tile: contiguous 4096 halves
#pragma unroll
    for (int i = 0; i < 4; i++) {
        int f = tid + i * 128;
        int r = f >> 3, c8 = (f & 7) * 8;
        *(uint4*)&Qsm[r][c8] = *(const uint4*)(Qp + f * 8);
    }
    __syncthreads();

    // preload Q fragments once
    unsigned qf[4][4];
    {
        int r = wid * 16 + g;
#pragma unroll
        for (int kk = 0; kk < 4; kk++) {
            qf[kk][0] = *(unsigned*)&Qsm[r][kk * 16 + tg * 2];
            qf[kk][1] = *(unsigned*)&Qsm[r + 8][kk * 16 + tg * 2];
            qf[kk][2] = *(unsigned*)&Qsm[r][kk * 16 + 8 + tg * 2];
            qf[kk][3] = *(unsigned*)&Qsm[r + 8][kk * 16 + 8 + tg * 2];
        }
    }

    float o[8][4] = {};
    float m0 = -1e30f, m1 = -1e30f, l0 = 0.f, l1 = 0.f;

    for (int it = 0; it < SEQ / 64; it++) {
        int par = it & 1;
        __syncthreads();
        if (tid == 0) maskAny[par ^ 1] = 0;
        // K tile (row-major [key][d], contiguous)
#pragma unroll
        for (int i = 0; i < 4; i++) {
            int f = tid + i * 128;
            int r = f >> 3, c8 = (f & 7) * 8;
            *(uint4*)&Ksm[r][c8] = *(const uint4*)(Kp + (size_t)it * 4096 + f * 8);
        }
        // V tile: already transposed in gmem, straight copy into [d][key]
#pragma unroll
        for (int i = 0; i < 4; i++) {
            int f = tid + i * 128;
            int d = f >> 3, k8 = (f & 7) * 8;
            *(uint4*)&Vtsm[d][k8] =
                *(const uint4*)(Vp + (size_t)d * SEQ + it * 64 + k8);
        }
        // mask tile + any-set flag
#pragma unroll
        for (int i = 0; i < 2; i++) {
            int f = tid + i * 128;
            int r = f >> 2, c16 = (f & 3) * 16;
            uint4 v = *(const uint4*)(Mp + (size_t)r * SEQ + it * 64 + c16);
            if (v.x | v.y | v.z | v.w) atomicOr(&maskAny[par], 1);
            *(uint4*)&Msm[r][c16] = v;
        }
        __syncthreads();

        // S = Q K^T
        float s[8][4] = {};
#pragma unroll
        for (int kk = 0; kk < 4; kk++) {
#pragma unroll
            for (int j = 0; j < 8; j++) {
                unsigned b0 = *(unsigned*)&Ksm[j * 8 + g][kk * 16 + tg * 2];
                unsigned b1 = *(unsigned*)&Ksm[j * 8 + g][kk * 16 + 8 + tg * 2];
                mma16816(s[j], qf[kk], b0, b1);
            }
        }

        if (maskAny[par]) {
            int r0 = wid * 16 + g;
#pragma unroll
            for (int j = 0; j < 8; j++) {
                int c = j * 8 + tg * 2;
                if (Msm[r0][c])         s[j][0] = -1e9f;
                if (Msm[r0][c + 1])     s[j][1] = -1e9f;
                if (Msm[r0 + 8][c])     s[j][2] = -1e9f;
                if (Msm[r0 + 8][c + 1]) s[j][3] = -1e9f;
            }
        }

        // online softmax (rows g and g+8 of this warp's 16)
        float rm0 = -1e30f, rm1 = -1e30f;
#pragma unroll
        for (int j = 0; j < 8; j++) {
            rm0 = fmaxf(rm0, fmaxf(s[j][0], s[j][1]));
            rm1 = fmaxf(rm1, fmaxf(s[j][2], s[j][3]));
        }
        rm0 = fmaxf(rm0, __shfl_xor_sync(0xffffffffu, rm0, 1));
        rm0 = fmaxf(rm0, __shfl_xor_sync(0xffffffffu, rm0, 2));
        rm1 = fmaxf(rm1, __shfl_xor_sync(0xffffffffu, rm1, 1));
        rm1 = fmaxf(rm1, __shfl_xor_sync(0xffffffffu, rm1, 2));
        float nm0 = fmaxf(m0, rm0), nm1 = fmaxf(m1, rm1);
        float a0 = __expf(m0 - nm0), a1 = __expf(m1 - nm1);
        float rs0 = 0.f, rs1 = 0.f;
#pragma unroll
        for (int j = 0; j < 8; j++) {
            s[j][0] = __expf(s[j][0] - nm0);
            s[j][1] = __expf(s[j][1] - nm0);
            s[j][2] = __expf(s[j][2] - nm1);
            s[j][3] = __expf(s[j][3] - nm1);
            rs0 += s[j][0] + s[j][1];
            rs1 += s[j][2] + s[j][3];
        }
        rs0 += __shfl_xor_sync(0xffffffffu, rs0, 1);
        rs0 += __shfl_xor_sync(0xffffffffu, rs0, 2);
        rs1 += __shfl_xor_sync(0xffffffffu, rs1, 1);
        rs1 += __shfl_xor_sync(0xffffffffu, rs1, 2);
        l0 = l0 * a0 + rs0;
        l1 = l1 * a1 + rs1;
        m0 = nm0; m1 = nm1;
#pragma unroll
        for (int j = 0; j < 8; j++) {
            o[j][0] *= a0; o[j][1] *= a0;
            o[j][2] *= a1; o[j][3] *= a1;
        }

        // P fragments straight from score registers
        unsigned pf[4][4];
#pragma unroll
        for (int t = 0; t < 4; t++) {
            pf[t][0] = packh2(s[2 * t][0], s[2 * t][1]);
            pf[t][1] = packh2(s[2 * t][2], s[2 * t][3]);
            pf[t][2] = packh2(s[2 * t + 1][0], s[2 * t + 1][1]);
            pf[t][3] = packh2(s[2 * t + 1][2], s[2 * t + 1][3]);
        }
        // O += P V
#pragma unroll
        for (int t = 0; t < 4; t++) {
#pragma unroll
            for (int j = 0; j < 8; j++) {
                unsigned b0 = *(unsigned*)&Vtsm[j * 8 + g][t * 16 + tg * 2];
                unsigned b1 = *(unsigned*)&Vtsm[j * 8 + g][t * 16 + 8 + tg * 2];
                mma16816(o[j], pf[t], b0, b1);
            }
        }
    }

    // finalize + store to [token, h*64+d] fp16
    float inv0 = 1.f / l0, inv1 = 1.f / l1;
    int srow = qt * 64 + wid * 16 + g;
#pragma unroll
    for (int j = 0; j < 8; j++) {
        int c = h * 64 + j * 8 + tg * 2;
        *(__half2*)(g_attn + (size_t)(b * SEQ + srow) * HID + c) =
            __floats2half2_rn(o[j][0] * inv0, o[j][1] * inv0);
        *(__half2*)(g_attn + (size_t)(b * SEQ + srow + 8) * HID + c) =
            __floats2half2_rn(o[j][2] * inv1, o[j][3] * inv1);
    }
}

// ---------------- output projection: out = attn(fp16) @ Wo^T -> fp32 ---------
__global__ __launch_bounds__(256) void gemm_out(float* __restrict__ out) {
    __shared__ __half Asm[128][40];
    __shared__ __half Bsm[64][40];

    const __half* W = g_W16[3];
    int tid = threadIdx.x, lane = tid & 31, wid = tid >> 5;
    int g = lane >> 2, tg = lane & 3;
    int wm = wid & 3, wn = wid >> 2;
    int rowB = blockIdx.y * 128, colB = blockIdx.x * 64;

    float acc[2][4][4] = {};

    for (int kb = 0; kb < HID; kb += 32) {
        __syncthreads();
#pragma unroll
        for (int i = 0; i < 2; i++) {
            int f = tid + i * 256;                 // 512 uint4 slots
            int r = f >> 2, c8 = (f & 3) * 8;
            *(uint4*)&Asm[r][c8] =
                *(const uint4*)(g_attn + (size_t)(rowB + r) * HID + kb + c8);
        }
        {
            int r = tid >> 2, c8 = (tid & 3) * 8;
            *(uint4*)&Bsm[r][c8] =
                *(const uint4*)(W + (size_t)(colB + r) * HID + kb + c8);
        }
        __syncthreads();

#pragma unroll
        for (int kk = 0; kk < 32; kk += 16) {
            unsigned a[2][4];
#pragma unroll
            for (int mi = 0; mi < 2; mi++) {
                int r = wm * 32 + mi * 16 + g;
                a[mi][0] = *(unsigned*)&Asm[r][kk + tg * 2];
                a[mi][1] = *(unsigned*)&Asm[r + 8][kk + tg * 2];
                a[mi][2] = *(unsigned*)&Asm[r][kk + 8 + tg * 2];
                a[mi][3] = *(unsigned*)&Asm[r + 8][kk + 8 + tg * 2];
            }
#pragma unroll
            for (int nj = 0; nj < 4; nj++) {
                int c = wn * 32 + nj * 8 + g;
                unsigned b0 = *(unsigned*)&Bsm[c][kk + tg * 2];
                unsigned b1 = *(unsigned*)&Bsm[c][kk + 8 + tg * 2];
                mma16816(acc[0][nj], a[0], b0, b1);
                mma16816(acc[1][nj], a[1], b0, b1);
            }
        }
    }

#pragma unroll
    for (int mi = 0; mi < 2; mi++) {
#pragma unroll
        for (int nj = 0; nj < 4; nj++) {
            int r0 = rowB + wm * 32 + mi * 16 + g;
            int c0 = colB + wn * 32 + nj * 8 + tg * 2;
            *(float2*)(out + (size_t)r0 * HID + c0) =
                make_float2(acc[mi][nj][0], acc[mi][nj][1]);
            *(float2*)(out + (size_t)(r0 + 8) * HID + c0) =
                make_float2(acc[mi][nj][2], acc[mi][nj][3]);
        }
    }
}

// ---------------- launch ------------------------------------------------------
extern "C" void kernel_launch(void* const* d_in, const int* in_sizes, int n_in,
                              void* d_out, int out_size) {
    (void)in_sizes; (void)n_in; (void)out_size;
    const float* q = (const float*)d_in[0];
    const float* k = (const float*)d_in[1];
    const float* v = (const float*)d_in[2];
    const unsigned char* mask = (const unsigned char*)d_in[3];
    const float* Wq = (const float*)d_in[4];
    const float* Wk = (const float*)d_in[5];
    const float* Wv = (const float*)d_in[6];
    const float* Wo = (const float*)d_in[7];
    float* out = (float*)d_out;

    cvt_weights<<<HID * HID / 4 / 256, 256>>>(Wq, Wk, Wv, Wo);

    dim3 gg(HID / 64, TOK / 128);           // (16, 32)
    gemm_head<<<gg, 256>>>(q, 0);
    gemm_head<<<gg, 256>>>(k, 1);
    gemm_head<<<gg, 256>>>(v, 2);

    flash<<<dim3(SEQ / 64, BATCH * HEADS), 128>>>(mask);

    gemm_out<<<gg, 256>>>(out);
}

// round 2
// speedup vs baseline: 1.6045x; 1.6045x over previous
#include <cuda_runtime.h>
#include <cuda_fp16.h>

#define HID   1024
#define HEADS 16
#define DK    64
#define BATCH 2
#define SEQ   2048
#define TOK   (BATCH * SEQ)   // 4096
#define QK_SCALE 0.125f

// ---------------- scratch --------------------------------------------------
__device__ __half g_W16[4][HID * HID];            // Wq,Wk,Wv,Wo fp16
__device__ __half g_X16[3][TOK * HID];            // q,k,v activations fp16
__device__ __half g_Qh[TOK * HID];                // [b,h,s,d] pre-scaled
__device__ __half g_Kh[TOK * HID];                // [b,h,s,d]
__device__ __half g_Vt[TOK * HID];                // [b,h,d,s]
__device__ __half g_attn[TOK * HID];              // [token, h*64+d]
__device__ int    g_maskAny;

// ---------------- ptx helpers ----------------------------------------------
__device__ __forceinline__ void mma16816(float* c, const unsigned* a,
                                         unsigned b0, unsigned b1) {
    asm volatile(
        "mma.sync.aligned.m16n8k16.row.col.f32.f16.f16.f32 "
        "{%0,%1,%2,%3}, {%4,%5,%6,%7}, {%8,%9}, {%0,%1,%2,%3};\n"
        : "+f"(c[0]), "+f"(c[1]), "+f"(c[2]), "+f"(c[3])
        : "r"(a[0]), "r"(a[1]), "r"(a[2]), "r"(a[3]), "r"(b0), "r"(b1));
}
__device__ __forceinline__ unsigned packh2(float x, float y) {
    __half2 h = __floats2half2_rn(x, y);
    return reinterpret_cast<unsigned&>(h);
}
__device__ __forceinline__ unsigned sptr(const void* p) {
    return (unsigned)__cvta_generic_to_shared(p);
}
__device__ __forceinline__ void cp16(void* s, const void* g) {
    asm volatile("cp.async.cg.shared.global [%0], [%1], 16;\n"
                 :: "r"(sptr(s)), "l"(g));
}
__device__ __forceinline__ void cp_commit() {
    asm volatile("cp.async.commit_group;\n");
}
template <int N> __device__ __forceinline__ void cp_wait() {
    asm volatile("cp.async.wait_group %0;\n" :: "n"(N));
}
__device__ __forceinline__ void ldsm4(unsigned* r, const __half* p) {
    asm volatile("ldmatrix.sync.aligned.m8n8.x4.shared.b16 {%0,%1,%2,%3}, [%4];\n"
                 : "=r"(r[0]), "=r"(r[1]), "=r"(r[2]), "=r"(r[3])
                 : "r"(sptr(p)));
}
// XOR swizzle for 64-half (128B) rows: conflict-free cp.async stores + LDSM
__device__ __forceinline__ int swz(int r, int k) {
    return r * 64 + ((((k >> 3) ^ r) & 7) << 3) + (k & 7);
}

// ---------------- prep kernels ---------------------------------------------
__global__ void cvt_weights(const float* __restrict__ wq, const float* __restrict__ wk,
                            const float* __restrict__ wv, const float* __restrict__ wo) {
    if (blockIdx.x == 0 && threadIdx.x == 0) g_maskAny = 0;
    int i = blockIdx.x * blockDim.x + threadIdx.x;
    const float4* srcs[4] = {(const float4*)wq, (const float4*)wk,
                             (const float4*)wv, (const float4*)wo};
#pragma unroll
    for (int w = 0; w < 4; w++) {
        float4 v = srcs[w][i];
        __half2* d = (__half2*)&g_W16[w][i * 4];
        d[0] = __floats2half2_rn(v.x, v.y);
        d[1] = __floats2half2_rn(v.z, v.w);
    }
}

__global__ void cvt_act(const float* __restrict__ q, const float* __restrict__ k,
                        const float* __restrict__ v) {
    int i = blockIdx.x * blockDim.x + threadIdx.x;
    const float4* srcs[3] = {(const float4*)q, (const float4*)k, (const float4*)v};
#pragma unroll
    for (int w = 0; w < 3; w++) {
        float4 t = srcs[w][i];
        __half2* d = (__half2*)&g_X16[w][i * 4];
        d[0] = __floats2half2_rn(t.x, t.y);
        d[1] = __floats2half2_rn(t.z, t.w);
    }
}

__global__ void mask_reduce(const uint4* __restrict__ m) {
    int i = blockIdx.x * blockDim.x + threadIdx.x;
    uint4 v = m[i];
    if (v.x | v.y | v.z | v.w) atomicOr(&g_maskAny, 1);
}

// ---------------- GEMM 128x128x64, 3-stage cp.async, ldmatrix ---------------
// MODE 0/1/2: A=g_X16[MODE], B=W[MODE], epilogue -> head layouts (Q scaled).
// MODE 3:     A=g_attn,      B=Wo,      epilogue -> fp32 out.
template <int MODE>
__global__ __launch_bounds__(256) void gemm128(float* __restrict__ out) {
    extern __shared__ __half sm[];   // 3 stages * (A 8192 + B 8192) halves
    const __half* A = (MODE == 0) ? g_X16[0] : (MODE == 1) ? g_X16[1]
                    : (MODE == 2) ? g_X16[2] : g_attn;
    const __half* W = g_W16[MODE];

    int tid = threadIdx.x, lane = tid & 31, wid = tid >> 5;
    int g = lane >> 2, tg = lane & 3;
    int wm = wid & 1, wn = wid >> 1;            // 2 (m) x 4 (n) warps
    int rowB = blockIdx.y * 128, colB = blockIdx.x * 128;

    // per-lane ldmatrix offsets
    int aro = lane & 15,               ako = (lane >> 4) << 3;
    int bro = ((lane >> 4) << 3) + (lane & 7), bko = ((lane >> 3) & 1) << 3;

    float acc[4][4][4] = {};

    auto load_stage = [&](int kb, int st) {
        __half* As = sm + st * 16384;
        __half* Bs = As + 8192;
        const __half* Ag = A + (size_t)rowB * HID + kb * 64;
        const __half* Bg = W + (size_t)colB * HID + kb * 64;
#pragma unroll
        for (int i = 0; i < 4; i++) {
            int cid = tid + i * 256;            // 1024 chunks of 8 halves
            int r = cid >> 3, c = cid & 7;
            int so = r * 64 + (((c ^ r) & 7) << 3);
            cp16(As + so, Ag + (size_t)r * HID + c * 8);
            cp16(Bs + so, Bg + (size_t)r * HID + c * 8);
        }
    };

    load_stage(0, 0); cp_commit();
    load_stage(1, 1); cp_commit();

    for (int kb = 0; kb < HID / 64; kb++) {
        cp_wait<1>(); __syncthreads();
        if (kb + 2 < HID / 64) { load_stage(kb + 2, (kb + 2) % 3); cp_commit(); }
        const __half* As = sm + (kb % 3) * 16384;
        const __half* Bs = As + 8192;
#pragma unroll
        for (int kk = 0; kk < 4; kk++) {
            unsigned a[4][4];
#pragma unroll
            for (int mi = 0; mi < 4; mi++)
                ldsm4(a[mi], As + swz(wm * 64 + mi * 16 + aro, kk * 16 + ako));
#pragma unroll
            for (int np = 0; np < 2; np++) {
                unsigned b[4];
                ldsm4(b, Bs + swz(wn * 32 + np * 16 + bro, kk * 16 + bko));
#pragma unroll
                for (int mi = 0; mi < 4; mi++) {
                    mma16816(acc[mi][np * 2],     a[mi], b[0], b[1]);
                    mma16816(acc[mi][np * 2 + 1], a[mi], b[2], b[3]);
                }
            }
        }
    }

    if (MODE == 3) {
#pragma unroll
        for (int mi = 0; mi < 4; mi++)
#pragma unroll
            for (int nj = 0; nj < 4; nj++) {
                int r0 = rowB + wm * 64 + mi * 16 + g;
                int c0 = colB + wn * 32 + nj * 8 + tg * 2;
                *(float2*)(out + (size_t)r0 * HID + c0) =
                    make_float2(acc[mi][nj][0], acc[mi][nj][1]);
                *(float2*)(out + (size_t)(r0 + 8) * HID + c0) =
                    make_float2(acc[mi][nj][2], acc[mi][nj][3]);
            }
    } else {
        float scale = (MODE == 0) ? QK_SCALE : 1.0f;
        __half* dst = (MODE == 0) ? g_Qh : (MODE == 1) ? g_Kh : g_Vt;
#pragma unroll
        for (int mi = 0; mi < 4; mi++)
#pragma unroll
            for (int nj = 0; nj < 4; nj++) {
                int r0 = rowB + wm * 64 + mi * 16 + g;
                int c0 = colB + wn * 32 + nj * 8 + tg * 2;
                int b = r0 >> 11, s = r0 & (SEQ - 1);
                int h = c0 >> 6, d = c0 & 63;
                int bh = b * HEADS + h;
                if (MODE == 2) {
                    size_t base = ((size_t)bh * DK + d) * SEQ + s;
                    dst[base]           = __float2half_rn(acc[mi][nj][0]);
                    dst[base + SEQ]     = __float2half_rn(acc[mi][nj][1]);
                    dst[base + 8]       = __float2half_rn(acc[mi][nj][2]);
                    dst[base + SEQ + 8] = __float2half_rn(acc[mi][nj][3]);
                } else {
                    size_t base = ((size_t)bh * SEQ + s) * DK + d;
                    *(__half2*)(dst + base) =
                        __floats2half2_rn(acc[mi][nj][0] * scale, acc[mi][nj][1] * scale);
                    *(__half2*)(dst + base + 8 * DK) =
                        __floats2half2_rn(acc[mi][nj][2] * scale, acc[mi][nj][3] * scale);
                }
            }
    }
}

// ---------------- flash attention: 64q x 64k tiles, 2-stage cp.async ---------
__global__ __launch_bounds__(128) void flash(const unsigned char* __restrict__ mask) {
    __shared__ __half Qs[64 * 64];
    __shared__ __half KVs[2][2][64 * 64];      // [stage][K=0/V=1]

    int tid = threadIdx.x, lane = tid & 31, wid = tid >> 5;
    int g = lane >> 2, tg = lane & 3;
    int bh = blockIdx.y, b = bh >> 4, h = bh & 15;
    int qt = blockIdx.x;

    const __half* Qp = g_Qh + (size_t)bh * SEQ * DK + (size_t)qt * 64 * DK;
    const __half* Kp = g_Kh + (size_t)bh * SEQ * DK;
    const __half* Vp = g_Vt + (size_t)bh * DK * SEQ;
    const unsigned char* Mp = mask + (size_t)b * SEQ * SEQ + (size_t)(qt * 64) * SEQ;
    int anyMask = g_maskAny;

    int aro = lane & 15,               ako = (lane >> 4) << 3;
    int bro = ((lane >> 4) << 3) + (lane & 7), bko = ((lane >> 3) & 1) << 3;

    auto load_kv = [&](int it, int st) {
#pragma unroll
        for (int i = 0; i < 4; i++) {
            int cid = tid + i * 128;            // 512 chunks
            int r = cid >> 3, c = cid & 7;
            int so = r * 64 + (((c ^ r) & 7) << 3);
            cp16(&KVs[st][0][so], Kp + (size_t)it * 4096 + cid * 8);
            cp16(&KVs[st][1][so], Vp + (size_t)r * SEQ + it * 64 + c * 8);
        }
    };

    // prologue: Q + stage 0
#pragma unroll
    for (int i = 0; i < 4; i++) {
        int cid = tid + i * 128;
        int r = cid >> 3, c = cid & 7;
        cp16(Qs + r * 64 + (((c ^ r) & 7) << 3), Qp + cid * 8);
    }
    load_kv(0, 0); cp_commit();
    cp_wait<0>(); __syncthreads();

    unsigned qf[4][4];
#pragma unroll
    for (int kk = 0; kk < 4; kk++)
        ldsm4(qf[kk], Qs + swz(wid * 16 + aro, kk * 16 + ako));

    float o[8][4] = {};
    float m0 = -1e30f, m1 = -1e30f, l0 = 0.f, l1 = 0.f;

    for (int it = 0; it < SEQ / 64; it++) {
        if (it > 0) { cp_wait<0>(); __syncthreads(); }
        if (it + 1 < SEQ / 64) { load_kv(it + 1, (it + 1) & 1); cp_commit(); }
        const __half* Ks = KVs[it & 1][0];
        const __half* Vs = KVs[it & 1][1];

        // S = Q K^T
        float s[8][4] = {};
#pragma unroll
        for (int kk = 0; kk < 4; kk++) {
#pragma unroll
            for (int np = 0; np < 4; np++) {
                unsigned bf[4];
                ldsm4(bf, Ks + swz(np * 16 + bro, kk * 16 + bko));
                mma16816(s[np * 2],     qf[kk], bf[0], bf[1]);
                mma16816(s[np * 2 + 1], qf[kk], bf[2], bf[3]);
            }
        }

        if (anyMask) {          // slow path, only when mask has any bits set
            int r0 = wid * 16 + g;
            const unsigned char* M0 = Mp + (size_t)r0 * SEQ + it * 64;
            const unsigned char* M1 = M0 + 8 * SEQ;
#pragma unroll
            for (int j = 0; j < 8; j++) {
                int c = j * 8 + tg * 2;
                if (M0[c])     s[j][0] = -1e9f;
                if (M0[c + 1]) s[j][1] = -1e9f;
                if (M1[c])     s[j][2] = -1e9f;
                if (M1[c + 1]) s[j][3] = -1e9f;
            }
        }

        // online softmax
        float rm0 = -1e30f, rm1 = -1e30f;
#pragma unroll
        for (int j = 0; j < 8; j++) {
            rm0 = fmaxf(rm0, fmaxf(s[j][0], s[j][1]));
            rm1 = fmaxf(rm1, fmaxf(s[j][2], s[j][3]));
        }
        rm0 = fmaxf(rm0, __shfl_xor_sync(0xffffffffu, rm0, 1));
        rm0 = fmaxf(rm0, __shfl_xor_sync(0xffffffffu, rm0, 2));
        rm1 = fmaxf(rm1, __shfl_xor_sync(0xffffffffu, rm1, 1));
        rm1 = fmaxf(rm1, __shfl_xor_sync(0xffffffffu, rm1, 2));
        float nm0 = fmaxf(m0, rm0), nm1 = fmaxf(m1, rm1);
        float a0 = __expf(m0 - nm0), a1 = __expf(m1 - nm1);
        float rs0 = 0.f, rs1 = 0.f;
#pragma unroll
        for (int j = 0; j < 8; j++) {
            s[j][0] = __expf(s[j][0] - nm0);
            s[j][1] = __expf(s[j][1] - nm0);
            s[j][2] = __expf(s[j][2] - nm1);
            s[j][3] = __expf(s[j][3] - nm1);
            rs0 += s[j][0] + s[j][1];
            rs1 += s[j][2] + s[j][3];
        }
        rs0 += __shfl_xor_sync(0xffffffffu, rs0, 1);
        rs0 += __shfl_xor_sync(0xffffffffu, rs0, 2);
        rs1 += __shfl_xor_sync(0xffffffffu, rs1, 1);
        rs1 += __shfl_xor_sync(0xffffffffu, rs1, 2);
        l0 = l0 * a0 + rs0;
        l1 = l1 * a1 + rs1;
        m0 = nm0; m1 = nm1;
#pragma unroll
        for (int j = 0; j < 8; j++) {
            o[j][0] *= a0; o[j][1] *= a0;
            o[j][2] *= a1; o[j][3] *= a1;
        }

        // P fragments from score regs
        unsigned pf[4][4];
#pragma unroll
        for (int t = 0; t < 4; t++) {
            pf[t][0] = packh2(s[2 * t][0],     s[2 * t][1]);
            pf[t][1] = packh2(s[2 * t][2],     s[2 * t][3]);
            pf[t][2] = packh2(s[2 * t + 1][0], s[2 * t + 1][1]);
            pf[t][3] = packh2(s[2 * t + 1][2], s[2 * t + 1][3]);
        }
        // O += P V   (V^T tile: n=d, k=keys)
#pragma unroll
        for (int t = 0; t < 4; t++) {
#pragma unroll
            for (int np = 0; np < 4; np++) {
                unsigned bf[4];
                ldsm4(bf, Vs + swz(np * 16 + bro, t * 16 + bko));
                mma16816(o[np * 2],     pf[t], bf[0], bf[1]);
                mma16816(o[np * 2 + 1], pf[t], bf[2], bf[3]);
            }
        }
    }

    float inv0 = 1.f / l0, inv1 = 1.f / l1;
    int srow = qt * 64 + wid * 16 + g;
#pragma unroll
    for (int j = 0; j < 8; j++) {
        int c = h * 64 + j * 8 + tg * 2;
        *(__half2*)(g_attn + (size_t)(b * SEQ + srow) * HID + c) =
            __floats2half2_rn(o[j][0] * inv0, o[j][1] * inv0);
        *(__half2*)(g_attn + (size_t)(b * SEQ + srow + 8) * HID + c) =
            __floats2half2_rn(o[j][2] * inv1, o[j][3] * inv1);
    }
}

// ---------------- launch -----------------------------------------------------
extern "C" void kernel_launch(void* const* d_in, const int* in_sizes, int n_in,
                              void* d_out, int out_size) {
    (void)in_sizes; (void)n_in; (void)out_size;
    const float* q = (const float*)d_in[0];
    const float* k = (const float*)d_in[1];
    const float* v = (const float*)d_in[2];
    const unsigned char* mask = (const unsigned char*)d_in[3];
    const float* Wq = (const float*)d_in[4];
    const float* Wk = (const float*)d_in[5];
    const float* Wv = (const float*)d_in[6];
    const float* Wo = (const float*)d_in[7];
    float* out = (float*)d_out;

    static bool attr_done = false;
    const int GEMM_SMEM = 3 * 16384 * 2;   // 96 KB
    if (!attr_done) {
        cudaFuncSetAttribute(gemm128<0>, cudaFuncAttributeMaxDynamicSharedMemorySize, GEMM_SMEM);
        cudaFuncSetAttribute(gemm128<1>, cudaFuncAttributeMaxDynamicSharedMemorySize, GEMM_SMEM);
        cudaFuncSetAttribute(gemm128<2>, cudaFuncAttributeMaxDynamicSharedMemorySize, GEMM_SMEM);
        cudaFuncSetAttribute(gemm128<3>, cudaFuncAttributeMaxDynamicSharedMemorySize, GEMM_SMEM);
        attr_done = true;
    }

    cvt_weights<<<HID * HID / 4 / 256, 256>>>(Wq, Wk, Wv, Wo);
    mask_reduce<<<(BATCH * SEQ * SEQ / 16) / 256, 256>>>((const uint4*)mask);
    cvt_act<<<TOK * HID / 4 / 256, 256>>>(q, k, v);

    dim3 gg(HID / 128, TOK / 128);          // (8, 32)
    gemm128<0><<<gg, 256, GEMM_SMEM>>>(nullptr);
    gemm128<1><<<gg, 256, GEMM_SMEM>>>(nullptr);
    gemm128<2><<<gg, 256, GEMM_SMEM>>>(nullptr);

    flash<<<dim3(SEQ / 64, BATCH * HEADS), 128>>>(mask);

    gemm128<3><<<gg, 256, GEMM_SMEM>>>(out);
}